// round 6
// baseline (speedup 1.0000x reference)
#include <cuda_runtime.h>
#include <cuda_bf16.h>

#define N_NODES 100000
#define N_EDGES 1000000
#define HID 64
#define SCAN_BS 512
#define NB_SCAN ((N_NODES + SCAN_BS - 1) / SCAN_BS)   // 196

#define GT 256          // nodes per fused block tile
#define XLD 72          // padded X row (floats), 16B-aligned rows
#define WLD 68          // padded W row
#define SMEM_FUSED ((GT * XLD + HID * WLD) * 4)        // 91136 B

// Scratch (device globals: allocation-free per harness rules)
__device__ __align__(16) float g_buf[N_NODES * HID];   // conv2 transform out
__device__ __align__(16) float h_buf[N_NODES * HID];   // conv3 transform out
__device__ __align__(16) float px_buf[N_NODES * 2];    // dinv * x
__device__ __align__(16) float t_buf[N_NODES * 2];     // conv1 aggregated (width 2)
__device__ float dinv_buf[N_NODES];
__device__ int   deg_buf[N_NODES];
__device__ int   incl_buf[N_NODES];
__device__ int   blksum_buf[NB_SCAN];
__device__ int   blkoff_buf[NB_SCAN];
__device__ int   csr_off[N_NODES + 1];
__device__ int   cursor_buf[N_NODES];
__device__ int   csr_row[N_EDGES];

// ---------------- f32x2 packed helpers ----------------
__device__ __forceinline__ unsigned long long ffma2(unsigned long long a,
                                                    unsigned long long b,
                                                    unsigned long long c) {
    unsigned long long d;
    asm("fma.rn.f32x2 %0, %1, %2, %3;" : "=l"(d) : "l"(a), "l"(b), "l"(c));
    return d;
}
__device__ __forceinline__ unsigned long long bcast2(float x) {
    unsigned long long d;
    asm("mov.b64 %0, {%1, %1};" : "=l"(d) : "f"(x));
    return d;
}
__device__ __forceinline__ float2 unpk(unsigned long long v) {
    float lo, hi;
    asm("mov.b64 {%0, %1}, %2;" : "=f"(lo), "=f"(hi) : "l"(v));
    return make_float2(lo, hi);
}

// ---------------- degree / CSR ----------------
__global__ void k_zero_deg() {
    int i = blockIdx.x * blockDim.x + threadIdx.x;
    if (i < N_NODES) deg_buf[i] = 0;
}

__global__ void k_count_deg(const int* __restrict__ ei) {
    int e = blockIdx.x * blockDim.x + threadIdx.x;
    if (e < N_EDGES) atomicAdd(&deg_buf[ei[N_EDGES + e]], 1);
}

__global__ void k_scan1() {
    __shared__ int sh[SCAN_BS];
    int t = threadIdx.x;
    int i = blockIdx.x * SCAN_BS + t;
    int v = (i < N_NODES) ? deg_buf[i] : 0;
    sh[t] = v;
    __syncthreads();
    for (int off = 1; off < SCAN_BS; off <<= 1) {
        int u = (t >= off) ? sh[t - off] : 0;
        __syncthreads();
        sh[t] += u;
        __syncthreads();
    }
    if (i < N_NODES) incl_buf[i] = sh[t];
    if (t == SCAN_BS - 1) blksum_buf[blockIdx.x] = sh[t];
}

__global__ void k_scan2() {
    __shared__ int warp_sums[8];
    int t = threadIdx.x;
    int lane = t & 31, w = t >> 5;
    int v = (t < NB_SCAN) ? blksum_buf[t] : 0;
    int s = v;
#pragma unroll
    for (int o = 1; o < 32; o <<= 1) {
        int u = __shfl_up_sync(0xffffffffu, s, o);
        if (lane >= o) s += u;
    }
    if (lane == 31) warp_sums[w] = s;
    __syncthreads();
    if (w == 0) {
        int ws = (lane < 8) ? warp_sums[lane] : 0;
#pragma unroll
        for (int o = 1; o < 8; o <<= 1) {
            int u = __shfl_up_sync(0xffffffffu, ws, o);
            if (lane >= o) ws += u;
        }
        if (lane < 8) warp_sums[lane] = ws;
    }
    __syncthreads();
    int base = (w > 0) ? warp_sums[w - 1] : 0;
    if (t < NB_SCAN) blkoff_buf[t] = base + s - v;
}

__global__ void k_scan3(const float* __restrict__ x) {   // + fused px
    int i = blockIdx.x * blockDim.x + threadIdx.x;
    if (i < N_NODES) {
        int d = deg_buf[i];
        int excl = incl_buf[i] - d + blkoff_buf[i / SCAN_BS];
        csr_off[i] = excl;
        cursor_buf[i] = excl;
        float di = rsqrtf((float)(d + 1));
        dinv_buf[i] = di;
        float2 xv = ((const float2*)x)[i];
        ((float2*)px_buf)[i] = make_float2(di * xv.x, di * xv.y);
        if (i == 0) csr_off[N_NODES] = N_EDGES;
    }
}

__global__ void k_fill(const int* __restrict__ ei) {
    int e = blockIdx.x * blockDim.x + threadIdx.x;
    if (e < N_EDGES) {
        int r = ei[e];
        int c = ei[N_EDGES + e];
        int pos = atomicAdd(&cursor_buf[c], 1);
        csr_row[pos] = r;
    }
}

// ---------------- width-2 aggregation for conv1 ----------------
__global__ void k_gather2() {
    int i = blockIdx.x * blockDim.x + threadIdx.x;
    if (i < N_NODES) {
        const float2* pp = (const float2*)px_buf;
        float2 acc = pp[i];
        int s = csr_off[i], e = csr_off[i + 1];
        int k = s;
        for (; k + 4 <= e; k += 4) {
            int r0 = csr_row[k], r1 = csr_row[k+1], r2 = csr_row[k+2], r3 = csr_row[k+3];
            float2 v0 = __ldg(&pp[r0]), v1 = __ldg(&pp[r1]);
            float2 v2 = __ldg(&pp[r2]), v3 = __ldg(&pp[r3]);
            acc.x += v0.x + v1.x + v2.x + v3.x;
            acc.y += v0.y + v1.y + v2.y + v3.y;
        }
        for (; k < e; k++) {
            float2 v = __ldg(&pp[csr_row[k]]);
            acc.x += v.x; acc.y += v.y;
        }
        float di = dinv_buf[i];
        ((float2*)t_buf)[i] = make_float2(di * acc.x, di * acc.y);
    }
}

// ---------------- shared fused-kernel pieces ----------------
__device__ __forceinline__ void load_W(const float* __restrict__ W, float* Ws) {
    for (int i = threadIdx.x; i < HID * HID / 4; i += 256) {
        float4 w4 = ((const float4*)W)[i];
        int k = (i * 4) >> 6, f = (i * 4) & 63;
        *(float4*)(Ws + k * WLD + f) = w4;
    }
}

// aggregate src rows via CSR into Xs (node-major), applying dinv+bias(+relu)
__device__ __forceinline__ void agg_into_smem(const float* __restrict__ src,
                                              const float* __restrict__ bias,
                                              int do_relu, int base, float* Xs) {
    int tid = threadIdx.x, w = tid >> 5, lane = tid & 31;
    float bx = bias[lane * 2], by = bias[lane * 2 + 1];
    const float2* gp = (const float2*)src;
    for (int n = w * 32; n < w * 32 + 32; n++) {
        int node = base + n;
        float ox = 0.f, oy = 0.f;
        if (node < N_NODES) {
            float2 acc = gp[node * 32 + lane];        // self loop
            int s = csr_off[node], e = csr_off[node + 1];
            int k = s;
            for (; k + 8 <= e; k += 8) {
                int r0 = csr_row[k],   r1 = csr_row[k+1], r2 = csr_row[k+2], r3 = csr_row[k+3];
                int r4 = csr_row[k+4], r5 = csr_row[k+5], r6 = csr_row[k+6], r7 = csr_row[k+7];
                float2 v0 = __ldg(&gp[r0 * 32 + lane]);
                float2 v1 = __ldg(&gp[r1 * 32 + lane]);
                float2 v2 = __ldg(&gp[r2 * 32 + lane]);
                float2 v3 = __ldg(&gp[r3 * 32 + lane]);
                float2 v4 = __ldg(&gp[r4 * 32 + lane]);
                float2 v5 = __ldg(&gp[r5 * 32 + lane]);
                float2 v6 = __ldg(&gp[r6 * 32 + lane]);
                float2 v7 = __ldg(&gp[r7 * 32 + lane]);
                acc.x += ((v0.x + v1.x) + (v2.x + v3.x)) + ((v4.x + v5.x) + (v6.x + v7.x));
                acc.y += ((v0.y + v1.y) + (v2.y + v3.y)) + ((v4.y + v5.y) + (v6.y + v7.y));
            }
            for (; k < e; k++) {
                float2 v = __ldg(&gp[csr_row[k] * 32 + lane]);
                acc.x += v.x; acc.y += v.y;
            }
            float di = dinv_buf[node];
            ox = di * acc.x + bx;
            oy = di * acc.y + by;
            if (do_relu) { ox = fmaxf(ox, 0.f); oy = fmaxf(oy, 0.f); }
        }
        *(float2*)(Xs + n * XLD + lane * 2) = make_float2(ox, oy);
    }
}

// 8x8 register tile GEMM with packed f32x2 FMA
__device__ __forceinline__ void gemm_core(const float* Xs, const float* Ws,
                                          unsigned long long* acc2) {
    int tid = threadIdx.x;
    int tn = tid & 7, tm = tid >> 3;
    const float* xbase = Xs + tm * 8 * XLD;
    const float* wbase = Ws + tn * 8;
#pragma unroll 4
    for (int k = 0; k < HID; k++) {
        union { float4 f; unsigned long long u[2]; } ua, ub;
        ua.f = *(const float4*)(wbase + k * WLD);
        ub.f = *(const float4*)(wbase + k * WLD + 4);
#pragma unroll
        for (int i = 0; i < 8; i++) {
            unsigned long long xx = bcast2(xbase[i * XLD + k]);
            acc2[i*4+0] = ffma2(xx, ua.u[0], acc2[i*4+0]);
            acc2[i*4+1] = ffma2(xx, ua.u[1], acc2[i*4+1]);
            acc2[i*4+2] = ffma2(xx, ub.u[0], acc2[i*4+2]);
            acc2[i*4+3] = ffma2(xx, ub.u[1], acc2[i*4+3]);
        }
    }
}

// ---------------- conv2: X = relu(t@W1+b1) on the fly; GEMM W2; g = dinv*X@W2 ----
__global__ __launch_bounds__(256, 2) void k_conv2(const float* __restrict__ W1,
                                                  const float* __restrict__ b1,
                                                  const float* __restrict__ W2) {
    extern __shared__ float sm[];
    float* Xs = sm;
    float* Ws = sm + GT * XLD;
    __shared__ float W1s[192];
    int tid = threadIdx.x;
    int base = blockIdx.x * GT;

    if (tid < 128) W1s[tid] = W1[tid];
    else if (tid < 192) W1s[tid] = b1[tid - 128];
    load_W(W2, Ws);

    // expand: node-major X rows
    float2 t = make_float2(0.f, 0.f);
    int node = base + tid;
    if (node < N_NODES) t = ((const float2*)t_buf)[node];
    __syncthreads();            // W1s ready
#pragma unroll
    for (int f4 = 0; f4 < 16; f4++) {
        float4 o;
        o.x = fmaxf(t.x * W1s[f4*4+0] + t.y * W1s[64+f4*4+0] + W1s[128+f4*4+0], 0.f);
        o.y = fmaxf(t.x * W1s[f4*4+1] + t.y * W1s[64+f4*4+1] + W1s[128+f4*4+1], 0.f);
        o.z = fmaxf(t.x * W1s[f4*4+2] + t.y * W1s[64+f4*4+2] + W1s[128+f4*4+2], 0.f);
        o.w = fmaxf(t.x * W1s[f4*4+3] + t.y * W1s[64+f4*4+3] + W1s[128+f4*4+3], 0.f);
        *(float4*)(Xs + tid * XLD + f4 * 4) = o;
    }
    __syncthreads();

    unsigned long long acc2[32];
#pragma unroll
    for (int i = 0; i < 32; i++) acc2[i] = 0ULL;
    gemm_core(Xs, Ws, acc2);

    int tn = tid & 7, tm = tid >> 3;
#pragma unroll
    for (int i = 0; i < 8; i++) {
        int nd = base + tm * 8 + i;
        if (nd < N_NODES) {
            float di = dinv_buf[nd];
            float2 p0 = unpk(acc2[i*4+0]), p1 = unpk(acc2[i*4+1]);
            float2 p2 = unpk(acc2[i*4+2]), p3 = unpk(acc2[i*4+3]);
            *(float4*)(g_buf + nd * HID + tn * 8)     = make_float4(p0.x*di, p0.y*di, p1.x*di, p1.y*di);
            *(float4*)(g_buf + nd * HID + tn * 8 + 4) = make_float4(p2.x*di, p2.y*di, p3.x*di, p3.y*di);
        }
    }
}

// ---------------- conv3: X = relu(dinv*agg(g)+b2); GEMM W3; h = dinv*X@W3 --------
__global__ __launch_bounds__(256, 2) void k_conv3(const float* __restrict__ b2,
                                                  const float* __restrict__ W3) {
    extern __shared__ float sm[];
    float* Xs = sm;
    float* Ws = sm + GT * XLD;
    int tid = threadIdx.x;
    int base = blockIdx.x * GT;

    load_W(W3, Ws);
    agg_into_smem(g_buf, b2, 1, base, Xs);
    __syncthreads();

    unsigned long long acc2[32];
#pragma unroll
    for (int i = 0; i < 32; i++) acc2[i] = 0ULL;
    gemm_core(Xs, Ws, acc2);

    int tn = tid & 7, tm = tid >> 3;
#pragma unroll
    for (int i = 0; i < 8; i++) {
        int nd = base + tm * 8 + i;
        if (nd < N_NODES) {
            float di = dinv_buf[nd];
            float2 p0 = unpk(acc2[i*4+0]), p1 = unpk(acc2[i*4+1]);
            float2 p2 = unpk(acc2[i*4+2]), p3 = unpk(acc2[i*4+3]);
            *(float4*)(h_buf + nd * HID + tn * 8)     = make_float4(p0.x*di, p0.y*di, p1.x*di, p1.y*di);
            *(float4*)(h_buf + nd * HID + tn * 8 + 4) = make_float4(p2.x*di, p2.y*di, p3.x*di, p3.y*di);
        }
    }
}

// ---------------- l45: X = dinv*agg(h)+b3; GEMM W4; out = relu(X@W4+b4)@W5 + b5 --
__global__ __launch_bounds__(256, 2) void k_l45(const float* __restrict__ b3,
                                                const float* __restrict__ W4,
                                                const float* __restrict__ b4,
                                                const float* __restrict__ W5,
                                                const float* __restrict__ b5,
                                                float* __restrict__ out) {
    extern __shared__ float sm[];
    float* Xs = sm;
    float* Ws = sm + GT * XLD;
    int tid = threadIdx.x;
    int base = blockIdx.x * GT;

    load_W(W4, Ws);
    agg_into_smem(h_buf, b3, 0, base, Xs);
    __syncthreads();

    unsigned long long acc2[32];
#pragma unroll
    for (int i = 0; i < 32; i++) acc2[i] = 0ULL;
    gemm_core(Xs, Ws, acc2);

    int tn = tid & 7, tm = tid >> 3;
    float4 b4a = __ldg((const float4*)(b4 + tn * 8));
    float4 b4b = __ldg((const float4*)(b4 + tn * 8 + 4));
    float4 w5a = __ldg((const float4*)(W5 + tn * 8));
    float4 w5b = __ldg((const float4*)(W5 + tn * 8 + 4));
    float bias5 = __ldg(b5);

#pragma unroll
    for (int i = 0; i < 8; i++) {
        float2 p0 = unpk(acc2[i*4+0]), p1 = unpk(acc2[i*4+1]);
        float2 p2 = unpk(acc2[i*4+2]), p3 = unpk(acc2[i*4+3]);
        float v = fmaxf(p0.x + b4a.x, 0.f) * w5a.x
                + fmaxf(p0.y + b4a.y, 0.f) * w5a.y
                + fmaxf(p1.x + b4a.z, 0.f) * w5a.z
                + fmaxf(p1.y + b4a.w, 0.f) * w5a.w
                + fmaxf(p2.x + b4b.x, 0.f) * w5b.x
                + fmaxf(p2.y + b4b.y, 0.f) * w5b.y
                + fmaxf(p3.x + b4b.z, 0.f) * w5b.z
                + fmaxf(p3.y + b4b.w, 0.f) * w5b.w;
        v += __shfl_xor_sync(0xffffffffu, v, 1);
        v += __shfl_xor_sync(0xffffffffu, v, 2);
        v += __shfl_xor_sync(0xffffffffu, v, 4);
        if (tn == 0) {
            int nd = base + tm * 8 + i;
            if (nd < N_NODES) out[nd] = v + bias5;
        }
    }
}

extern "C" void kernel_launch(void* const* d_in, const int* in_sizes, int n_in,
                              void* d_out, int out_size) {
    const float* x  = (const float*)d_in[0];
    const int*   ei = (const int*)d_in[1];     // edge_index int32
    const float* W1 = (const float*)d_in[3];
    const float* b1 = (const float*)d_in[4];
    const float* W2 = (const float*)d_in[5];
    const float* b2 = (const float*)d_in[6];
    const float* W3 = (const float*)d_in[7];
    const float* b3 = (const float*)d_in[8];
    const float* W4 = (const float*)d_in[9];
    const float* b4 = (const float*)d_in[10];
    const float* W5 = (const float*)d_in[11];
    const float* b5 = (const float*)d_in[12];
    float* out = (float*)d_out;

    static int smem_set = 0;
    if (!smem_set) {
        cudaFuncSetAttribute(k_conv2, cudaFuncAttributeMaxDynamicSharedMemorySize, SMEM_FUSED);
        cudaFuncSetAttribute(k_conv3, cudaFuncAttributeMaxDynamicSharedMemorySize, SMEM_FUSED);
        cudaFuncSetAttribute(k_l45,   cudaFuncAttributeMaxDynamicSharedMemorySize, SMEM_FUSED);
        smem_set = 1;
    }

    const int nbN = (N_NODES + 255) / 256;
    const int nbE = (N_EDGES + 255) / 256;
    const int nbG = (N_NODES + GT - 1) / GT;          // 391

    // CSR build + norm (+ px)
    k_zero_deg<<<nbN, 256>>>();
    k_count_deg<<<nbE, 256>>>(ei);
    k_scan1<<<NB_SCAN, SCAN_BS>>>();
    k_scan2<<<1, 256>>>();
    k_scan3<<<nbN, 256>>>(x);
    k_fill<<<nbE, 256>>>(ei);

    // conv1 aggregation (width 2)
    k_gather2<<<nbN, 256>>>();

    // fused layers
    k_conv2<<<nbG, 256, SMEM_FUSED>>>(W1, b1, W2);
    k_conv3<<<nbG, 256, SMEM_FUSED>>>(b2, W3);
    k_l45<<<nbG, 256, SMEM_FUSED>>>(b3, W4, b4, W5, b5, out);
}

// round 7
// speedup vs baseline: 1.5875x; 1.5875x over previous
#include <cuda_runtime.h>
#include <cuda_bf16.h>

#define N_NODES 100000
#define N_EDGES 1000000
#define HID 64
#define SCAN_BS 512
#define NB_SCAN ((N_NODES + SCAN_BS - 1) / SCAN_BS)   // 196

#define GT 256          // nodes per GEMM block tile
#define WLD 68          // padded W row
#define SMEM_GEMM ((HID * GT + HID * WLD) * 4)        // 82944 B

// Scratch (device globals: allocation-free per harness rules)
__device__ __align__(16) float g_buf[N_NODES * HID];   // transform out (gather source)
__device__ __align__(16) float h_buf[N_NODES * HID];   // aggregated layer output
__device__ __align__(16) float px_buf[N_NODES * 2];    // dinv * x
__device__ __align__(16) float t_buf[N_NODES * 2];     // conv1 aggregated (width 2)
__device__ float dinv_buf[N_NODES];
__device__ int   deg_buf[N_NODES];
__device__ int   incl_buf[N_NODES];
__device__ int   blksum_buf[NB_SCAN];
__device__ int   blkoff_buf[NB_SCAN];
__device__ int   csr_off[N_NODES + 1];
__device__ int   cursor_buf[N_NODES];
__device__ int   csr_row[N_EDGES];

// ---------------- f32x2 packed helpers ----------------
__device__ __forceinline__ unsigned long long ffma2(unsigned long long a,
                                                    unsigned long long b,
                                                    unsigned long long c) {
    unsigned long long d;
    asm("fma.rn.f32x2 %0, %1, %2, %3;" : "=l"(d) : "l"(a), "l"(b), "l"(c));
    return d;
}
__device__ __forceinline__ unsigned long long bcast2(float x) {
    unsigned long long d;
    asm("mov.b64 %0, {%1, %1};" : "=l"(d) : "f"(x));
    return d;
}
__device__ __forceinline__ float2 unpk(unsigned long long v) {
    float lo, hi;
    asm("mov.b64 {%0, %1}, %2;" : "=f"(lo), "=f"(hi) : "l"(v));
    return make_float2(lo, hi);
}

// ---------------- degree / CSR ----------------
__global__ void k_zero_deg() {
    int i = blockIdx.x * blockDim.x + threadIdx.x;
    if (i < N_NODES) deg_buf[i] = 0;
}

__global__ void k_count_deg(const int* __restrict__ ei) {
    int e = blockIdx.x * blockDim.x + threadIdx.x;
    if (e < N_EDGES) atomicAdd(&deg_buf[ei[N_EDGES + e]], 1);
}

__global__ void k_scan1() {
    __shared__ int sh[SCAN_BS];
    int t = threadIdx.x;
    int i = blockIdx.x * SCAN_BS + t;
    int v = (i < N_NODES) ? deg_buf[i] : 0;
    sh[t] = v;
    __syncthreads();
    for (int off = 1; off < SCAN_BS; off <<= 1) {
        int u = (t >= off) ? sh[t - off] : 0;
        __syncthreads();
        sh[t] += u;
        __syncthreads();
    }
    if (i < N_NODES) incl_buf[i] = sh[t];
    if (t == SCAN_BS - 1) blksum_buf[blockIdx.x] = sh[t];
}

__global__ void k_scan2() {
    __shared__ int warp_sums[8];
    int t = threadIdx.x;
    int lane = t & 31, w = t >> 5;
    int v = (t < NB_SCAN) ? blksum_buf[t] : 0;
    int s = v;
#pragma unroll
    for (int o = 1; o < 32; o <<= 1) {
        int u = __shfl_up_sync(0xffffffffu, s, o);
        if (lane >= o) s += u;
    }
    if (lane == 31) warp_sums[w] = s;
    __syncthreads();
    if (w == 0) {
        int ws = (lane < 8) ? warp_sums[lane] : 0;
#pragma unroll
        for (int o = 1; o < 8; o <<= 1) {
            int u = __shfl_up_sync(0xffffffffu, ws, o);
            if (lane >= o) ws += u;
        }
        if (lane < 8) warp_sums[lane] = ws;
    }
    __syncthreads();
    int base = (w > 0) ? warp_sums[w - 1] : 0;
    if (t < NB_SCAN) blkoff_buf[t] = base + s - v;
}

__global__ void k_scan3(const float* __restrict__ x) {   // + fused px
    int i = blockIdx.x * blockDim.x + threadIdx.x;
    if (i < N_NODES) {
        int d = deg_buf[i];
        int excl = incl_buf[i] - d + blkoff_buf[i / SCAN_BS];
        csr_off[i] = excl;
        cursor_buf[i] = excl;
        float di = rsqrtf((float)(d + 1));
        dinv_buf[i] = di;
        float2 xv = ((const float2*)x)[i];
        ((float2*)px_buf)[i] = make_float2(di * xv.x, di * xv.y);
        if (i == 0) csr_off[N_NODES] = N_EDGES;
    }
}

__global__ void k_fill(const int* __restrict__ ei) {
    int e = blockIdx.x * blockDim.x + threadIdx.x;
    if (e < N_EDGES) {
        int r = ei[e];
        int c = ei[N_EDGES + e];
        int pos = atomicAdd(&cursor_buf[c], 1);
        csr_row[pos] = r;
    }
}

// ---------------- width-2 aggregation for conv1 ----------------
__global__ void k_gather2() {
    int i = blockIdx.x * blockDim.x + threadIdx.x;
    if (i < N_NODES) {
        const float2* pp = (const float2*)px_buf;
        float2 acc = pp[i];
        int s = csr_off[i], e = csr_off[i + 1];
        int k = s;
        for (; k + 4 <= e; k += 4) {
            int r0 = csr_row[k], r1 = csr_row[k+1], r2 = csr_row[k+2], r3 = csr_row[k+3];
            float2 v0 = __ldg(&pp[r0]), v1 = __ldg(&pp[r1]);
            float2 v2 = __ldg(&pp[r2]), v3 = __ldg(&pp[r3]);
            acc.x += v0.x + v1.x + v2.x + v3.x;
            acc.y += v0.y + v1.y + v2.y + v3.y;
        }
        for (; k < e; k++) {
            float2 v = __ldg(&pp[csr_row[k]]);
            acc.x += v.x; acc.y += v.y;
        }
        float di = dinv_buf[i];
        ((float2*)t_buf)[i] = make_float2(di * acc.x, di * acc.y);
    }
}

// ---------------- fused gather-aggregate + finalize (width 64) ----------------
// h[i] = relu?( dinv[i] * (g[i] + sum_{j in N(i)} g[j]) + b )
__global__ void k_gather(const float* __restrict__ bias, int do_relu) {
    int w = (blockIdx.x * blockDim.x + threadIdx.x) >> 5;
    int lane = threadIdx.x & 31;
    if (w >= N_NODES) return;

    const float2* gp = (const float2*)g_buf;
    float2 acc = gp[w * 32 + lane];            // self loop
    int s = csr_off[w], e = csr_off[w + 1];

    int k = s;
    for (; k + 8 <= e; k += 8) {
        int r0 = csr_row[k],   r1 = csr_row[k+1], r2 = csr_row[k+2], r3 = csr_row[k+3];
        int r4 = csr_row[k+4], r5 = csr_row[k+5], r6 = csr_row[k+6], r7 = csr_row[k+7];
        float2 v0 = __ldg(&gp[r0 * 32 + lane]);
        float2 v1 = __ldg(&gp[r1 * 32 + lane]);
        float2 v2 = __ldg(&gp[r2 * 32 + lane]);
        float2 v3 = __ldg(&gp[r3 * 32 + lane]);
        float2 v4 = __ldg(&gp[r4 * 32 + lane]);
        float2 v5 = __ldg(&gp[r5 * 32 + lane]);
        float2 v6 = __ldg(&gp[r6 * 32 + lane]);
        float2 v7 = __ldg(&gp[r7 * 32 + lane]);
        acc.x += ((v0.x + v1.x) + (v2.x + v3.x)) + ((v4.x + v5.x) + (v6.x + v7.x));
        acc.y += ((v0.y + v1.y) + (v2.y + v3.y)) + ((v4.y + v5.y) + (v6.y + v7.y));
    }
    for (; k < e; k++) {
        float2 v = __ldg(&gp[csr_row[k] * 32 + lane]);
        acc.x += v.x;
        acc.y += v.y;
    }

    float di = dinv_buf[w];
    float o0 = di * acc.x + bias[lane * 2];
    float o1 = di * acc.y + bias[lane * 2 + 1];
    if (do_relu) { o0 = fmaxf(o0, 0.f); o1 = fmaxf(o1, 0.f); }
    ((float2*)h_buf)[w * 32 + lane] = make_float2(o0, o1);
}

// ---------------- GEMM helpers (k-major Xs, FFMA2 core) ----------------
__device__ __forceinline__ void load_W(const float* __restrict__ W, float* Ws) {
    for (int i = threadIdx.x; i < HID * HID / 4; i += 256) {
        float4 w4 = ((const float4*)W)[i];
        int k = (i * 4) >> 6, f = (i * 4) & 63;
        *(float4*)(Ws + k * WLD + f) = w4;
    }
}

// load X tile from h_buf transposed into k-major smem (conflict-free STS)
__device__ __forceinline__ void load_X_T(int base, float* Xs) {
    int tid = threadIdx.x;
    int node = base + tid;
    if (node < N_NODES) {
        const float4* src = (const float4*)(h_buf + node * HID);
#pragma unroll
        for (int kk = 0; kk < 16; kk++) {
            float4 v = src[kk];
            Xs[(kk * 4 + 0) * GT + tid] = v.x;
            Xs[(kk * 4 + 1) * GT + tid] = v.y;
            Xs[(kk * 4 + 2) * GT + tid] = v.z;
            Xs[(kk * 4 + 3) * GT + tid] = v.w;
        }
    } else {
#pragma unroll
        for (int kk = 0; kk < HID; kk++) Xs[kk * GT + tid] = 0.f;
    }
}

// acc2[p*8+j] = packed (out[n=tm*8+2p][f=tn*8+j], out[n=tm*8+2p+1][f=tn*8+j])
__device__ __forceinline__ void gemm_core_f2(const float* Xs, const float* Ws,
                                             unsigned long long* acc2) {
    int tid = threadIdx.x;
    int tn = tid & 7, tm = tid >> 3;
    const float* xbase = Xs + tm * 8;
    const float* wbase = Ws + tn * 8;
#pragma unroll 4
    for (int k = 0; k < HID; k++) {
        union { float4 f; unsigned long long u[2]; } xa, xb;
        xa.f = *(const float4*)(xbase + k * GT);        // nodes 0..3 at this k
        xb.f = *(const float4*)(xbase + k * GT + 4);    // nodes 4..7
        float4 wa = *(const float4*)(wbase + k * WLD);
        float4 wb = *(const float4*)(wbase + k * WLD + 4);
        float wr[8] = {wa.x, wa.y, wa.z, wa.w, wb.x, wb.y, wb.z, wb.w};
#pragma unroll
        for (int j = 0; j < 8; j++) {
            unsigned long long wj = bcast2(wr[j]);
            acc2[0*8+j] = ffma2(xa.u[0], wj, acc2[0*8+j]);
            acc2[1*8+j] = ffma2(xa.u[1], wj, acc2[1*8+j]);
            acc2[2*8+j] = ffma2(xb.u[0], wj, acc2[2*8+j]);
            acc2[3*8+j] = ffma2(xb.u[1], wj, acc2[3*8+j]);
        }
    }
}

// write conv epilogue: g[n][f] = dinv[n] * acc
__device__ __forceinline__ void conv_epilogue(int base, const unsigned long long* acc2) {
    int tid = threadIdx.x;
    int tn = tid & 7, tm = tid >> 3;
#pragma unroll
    for (int p = 0; p < 4; p++) {
        float lo[8], hi[8];
#pragma unroll
        for (int j = 0; j < 8; j++) {
            float2 v = unpk(acc2[p*8+j]);
            lo[j] = v.x; hi[j] = v.y;
        }
        int n0 = base + tm * 8 + 2 * p;
        int n1 = n0 + 1;
        if (n0 < N_NODES) {
            float d0 = dinv_buf[n0];
            *(float4*)(g_buf + n0 * HID + tn * 8)     = make_float4(lo[0]*d0, lo[1]*d0, lo[2]*d0, lo[3]*d0);
            *(float4*)(g_buf + n0 * HID + tn * 8 + 4) = make_float4(lo[4]*d0, lo[5]*d0, lo[6]*d0, lo[7]*d0);
        }
        if (n1 < N_NODES) {
            float d1 = dinv_buf[n1];
            *(float4*)(g_buf + n1 * HID + tn * 8)     = make_float4(hi[0]*d1, hi[1]*d1, hi[2]*d1, hi[3]*d1);
            *(float4*)(g_buf + n1 * HID + tn * 8 + 4) = make_float4(hi[4]*d1, hi[5]*d1, hi[6]*d1, hi[7]*d1);
        }
    }
}

// ---------------- conv2: expand t via W1 in-reg -> k-major smem; GEMM W2 ---------
__global__ __launch_bounds__(256, 2) void k_conv2(const float* __restrict__ W1,
                                                  const float* __restrict__ b1,
                                                  const float* __restrict__ W2) {
    extern __shared__ float sm[];
    float* Xs = sm;                  // [HID][GT] k-major
    float* Ws = sm + HID * GT;       // [HID][WLD]
    __shared__ float W1s[192];
    int tid = threadIdx.x;
    int base = blockIdx.x * GT;

    if (tid < 128) W1s[tid] = W1[tid];
    else if (tid < 192) W1s[tid] = b1[tid - 128];
    load_W(W2, Ws);

    float2 t = make_float2(0.f, 0.f);
    int node = base + tid;
    bool valid = node < N_NODES;
    if (valid) t = ((const float2*)t_buf)[node];
    __syncthreads();                 // W1s ready
#pragma unroll
    for (int k = 0; k < HID; k++) {
        float v = valid ? fmaxf(t.x * W1s[k] + t.y * W1s[64 + k] + W1s[128 + k], 0.f) : 0.f;
        Xs[k * GT + tid] = v;        // conflict-free: consecutive tid
    }
    __syncthreads();

    unsigned long long acc2[32];
#pragma unroll
    for (int i = 0; i < 32; i++) acc2[i] = 0ULL;
    gemm_core_f2(Xs, Ws, acc2);
    conv_epilogue(base, acc2);
}

// ---------------- conv3: X from h_buf; GEMM W3; g = dinv * X@W3 ------------------
__global__ __launch_bounds__(256, 2) void k_conv3(const float* __restrict__ W3) {
    extern __shared__ float sm[];
    float* Xs = sm;
    float* Ws = sm + HID * GT;
    int base = blockIdx.x * GT;

    load_W(W3, Ws);
    load_X_T(base, Xs);
    __syncthreads();

    unsigned long long acc2[32];
#pragma unroll
    for (int i = 0; i < 32; i++) acc2[i] = 0ULL;
    gemm_core_f2(Xs, Ws, acc2);
    conv_epilogue(base, acc2);
}

// ---------------- l45: X from h_buf; GEMM W4; out = relu(acc+b4) . W5 + b5 -------
__global__ __launch_bounds__(256, 2) void k_l45(const float* __restrict__ W4,
                                                const float* __restrict__ b4,
                                                const float* __restrict__ W5,
                                                const float* __restrict__ b5,
                                                float* __restrict__ out) {
    extern __shared__ float sm[];
    float* Xs = sm;
    float* Ws = sm + HID * GT;
    int tid = threadIdx.x;
    int base = blockIdx.x * GT;

    load_W(W4, Ws);
    load_X_T(base, Xs);
    __syncthreads();

    unsigned long long acc2[32];
#pragma unroll
    for (int i = 0; i < 32; i++) acc2[i] = 0ULL;
    gemm_core_f2(Xs, Ws, acc2);

    int tn = tid & 7, tm = tid >> 3;
    float4 b4a = __ldg((const float4*)(b4 + tn * 8));
    float4 b4b = __ldg((const float4*)(b4 + tn * 8 + 4));
    float4 w5a = __ldg((const float4*)(W5 + tn * 8));
    float4 w5b = __ldg((const float4*)(W5 + tn * 8 + 4));
    float br[8] = {b4a.x, b4a.y, b4a.z, b4a.w, b4b.x, b4b.y, b4b.z, b4b.w};
    float wr[8] = {w5a.x, w5a.y, w5a.z, w5a.w, w5b.x, w5b.y, w5b.z, w5b.w};
    float bias5 = __ldg(b5);

#pragma unroll
    for (int p = 0; p < 4; p++) {
        float v0 = 0.f, v1 = 0.f;
#pragma unroll
        for (int j = 0; j < 8; j++) {
            float2 v = unpk(acc2[p*8+j]);
            v0 += fmaxf(v.x + br[j], 0.f) * wr[j];
            v1 += fmaxf(v.y + br[j], 0.f) * wr[j];
        }
        v0 += __shfl_xor_sync(0xffffffffu, v0, 1);
        v0 += __shfl_xor_sync(0xffffffffu, v0, 2);
        v0 += __shfl_xor_sync(0xffffffffu, v0, 4);
        v1 += __shfl_xor_sync(0xffffffffu, v1, 1);
        v1 += __shfl_xor_sync(0xffffffffu, v1, 2);
        v1 += __shfl_xor_sync(0xffffffffu, v1, 4);
        if (tn == 0) {
            int n0 = base + tm * 8 + 2 * p;
            if (n0 < N_NODES)     out[n0]     = v0 + bias5;
            if (n0 + 1 < N_NODES) out[n0 + 1] = v1 + bias5;
        }
    }
}

extern "C" void kernel_launch(void* const* d_in, const int* in_sizes, int n_in,
                              void* d_out, int out_size) {
    const float* x  = (const float*)d_in[0];
    const int*   ei = (const int*)d_in[1];     // edge_index int32
    const float* W1 = (const float*)d_in[3];
    const float* b1 = (const float*)d_in[4];
    const float* W2 = (const float*)d_in[5];
    const float* b2 = (const float*)d_in[6];
    const float* W3 = (const float*)d_in[7];
    const float* b3 = (const float*)d_in[8];
    const float* W4 = (const float*)d_in[9];
    const float* b4 = (const float*)d_in[10];
    const float* W5 = (const float*)d_in[11];
    const float* b5 = (const float*)d_in[12];
    float* out = (float*)d_out;

    static int smem_set = 0;
    if (!smem_set) {
        cudaFuncSetAttribute(k_conv2, cudaFuncAttributeMaxDynamicSharedMemorySize, SMEM_GEMM);
        cudaFuncSetAttribute(k_conv3, cudaFuncAttributeMaxDynamicSharedMemorySize, SMEM_GEMM);
        cudaFuncSetAttribute(k_l45,   cudaFuncAttributeMaxDynamicSharedMemorySize, SMEM_GEMM);
        smem_set = 1;
    }

    const int nbN = (N_NODES + 255) / 256;
    const int nbE = (N_EDGES + 255) / 256;
    const int nbG = (N_NODES + GT - 1) / GT;          // 391
    const int nbW = (N_NODES * 32 + 255) / 256;       // 1 warp per node

    // CSR build + norm (+ px)
    k_zero_deg<<<nbN, 256>>>();
    k_count_deg<<<nbE, 256>>>(ei);
    k_scan1<<<NB_SCAN, SCAN_BS>>>();
    k_scan2<<<1, 256>>>();
    k_scan3<<<nbN, 256>>>(x);
    k_fill<<<nbE, 256>>>(ei);

    // conv1 aggregation (width 2)
    k_gather2<<<nbN, 256>>>();

    // conv2: expand+GEMM -> g ; gather -> h
    k_conv2<<<nbG, 256, SMEM_GEMM>>>(W1, b1, W2);
    k_gather<<<nbW, 256>>>(b2, 1);
    // conv3: GEMM -> g ; gather -> h
    k_conv3<<<nbG, 256, SMEM_GEMM>>>(W3);
    k_gather<<<nbW, 256>>>(b3, 0);
    // layers 4+5 fused
    k_l45<<<nbG, 256, SMEM_GEMM>>>(W4, b4, W5, b5, out);
}

// round 8
// speedup vs baseline: 1.6708x; 1.0525x over previous
#include <cuda_runtime.h>
#include <cuda_fp16.h>

#define N_NODES 100000
#define N_EDGES 1000000
#define HID 64
#define SCAN_BS 512
#define NB_SCAN ((N_NODES + SCAN_BS - 1) / SCAN_BS)   // 196

#define GT 256          // nodes per GEMM block tile
#define WLD 68          // padded W row
#define SMEM_GEMM ((HID * GT + HID * WLD) * 4)        // 82944 B

// Scratch (device globals: allocation-free per harness rules)
__device__ __align__(16) __half g_half[N_NODES * HID]; // transform out, fp16 (gather source)
__device__ __align__(16) float h_buf[N_NODES * HID];   // aggregated layer output (fp32)
__device__ __align__(16) float px_buf[N_NODES * 2];    // dinv * x
__device__ __align__(16) float t_buf[N_NODES * 2];     // conv1 aggregated (width 2)
__device__ float dinv_buf[N_NODES];
__device__ int   deg_buf[N_NODES];
__device__ int   csr_off[N_NODES];     // segment starts (unordered across blocks)
__device__ int   cursor_buf[N_NODES];
__device__ int   csr_row[N_EDGES];
__device__ int   g_base_ctr;

// ---------------- f32x2 packed helpers ----------------
__device__ __forceinline__ unsigned long long ffma2(unsigned long long a,
                                                    unsigned long long b,
                                                    unsigned long long c) {
    unsigned long long d;
    asm("fma.rn.f32x2 %0, %1, %2, %3;" : "=l"(d) : "l"(a), "l"(b), "l"(c));
    return d;
}
__device__ __forceinline__ unsigned long long bcast2(float x) {
    unsigned long long d;
    asm("mov.b64 %0, {%1, %1};" : "=l"(d) : "f"(x));
    return d;
}
__device__ __forceinline__ float2 unpk(unsigned long long v) {
    float lo, hi;
    asm("mov.b64 {%0, %1}, %2;" : "=f"(lo), "=f"(hi) : "l"(v));
    return make_float2(lo, hi);
}

// ---------------- degree ----------------
__global__ void k_zero_deg() {
    int i = blockIdx.x * blockDim.x + threadIdx.x;
    if (i < N_NODES) deg_buf[i] = 0;
    if (i == 0) g_base_ctr = 0;
}

__global__ void k_count_deg(const int* __restrict__ ei) {
    int e = blockIdx.x * blockDim.x + threadIdx.x;
    if (e < N_EDGES) atomicAdd(&deg_buf[ei[N_EDGES + e]], 1);
}

// ---------------- single-kernel scan: unordered block segments via atomic base ----
__global__ void k_scan_fused(const float* __restrict__ x) {
    __shared__ int wsum[16];
    __shared__ int sbase;
    int t = threadIdx.x;                      // 512 threads
    int i = blockIdx.x * SCAN_BS + t;
    int lane = t & 31, w = t >> 5;
    int d = (i < N_NODES) ? deg_buf[i] : 0;

    int s = d;
#pragma unroll
    for (int o = 1; o < 32; o <<= 1) {
        int u = __shfl_up_sync(0xffffffffu, s, o);
        if (lane >= o) s += u;
    }
    if (lane == 31) wsum[w] = s;
    __syncthreads();
    if (w == 0) {
        int v = (lane < 16) ? wsum[lane] : 0;
#pragma unroll
        for (int o = 1; o < 16; o <<= 1) {
            int u = __shfl_up_sync(0xffffffffu, v, o);
            if (lane >= o) v += u;
        }
        if (lane < 16) wsum[lane] = v;        // inclusive warp sums
    }
    __syncthreads();
    if (t == 0) sbase = atomicAdd(&g_base_ctr, wsum[15]);
    __syncthreads();

    int warpbase = (w > 0) ? wsum[w - 1] : 0;
    int excl = sbase + warpbase + s - d;
    if (i < N_NODES) {
        csr_off[i] = excl;
        cursor_buf[i] = excl;
        float di = rsqrtf((float)(d + 1));
        dinv_buf[i] = di;
        float2 xv = ((const float2*)x)[i];
        ((float2*)px_buf)[i] = make_float2(di * xv.x, di * xv.y);
    }
}

__global__ void k_fill(const int* __restrict__ ei) {
    int e = blockIdx.x * blockDim.x + threadIdx.x;
    if (e < N_EDGES) {
        int r = ei[e];
        int c = ei[N_EDGES + e];
        int pos = atomicAdd(&cursor_buf[c], 1);
        csr_row[pos] = r;
    }
}

// ---------------- width-2 aggregation for conv1 ----------------
__global__ void k_gather2() {
    int i = blockIdx.x * blockDim.x + threadIdx.x;
    if (i < N_NODES) {
        const float2* pp = (const float2*)px_buf;
        float2 acc = pp[i];
        int s = csr_off[i], e = s + deg_buf[i];
        int k = s;
        for (; k + 4 <= e; k += 4) {
            int r0 = csr_row[k], r1 = csr_row[k+1], r2 = csr_row[k+2], r3 = csr_row[k+3];
            float2 v0 = __ldg(&pp[r0]), v1 = __ldg(&pp[r1]);
            float2 v2 = __ldg(&pp[r2]), v3 = __ldg(&pp[r3]);
            acc.x += v0.x + v1.x + v2.x + v3.x;
            acc.y += v0.y + v1.y + v2.y + v3.y;
        }
        for (; k < e; k++) {
            float2 v = __ldg(&pp[csr_row[k]]);
            acc.x += v.x; acc.y += v.y;
        }
        float di = dinv_buf[i];
        ((float2*)t_buf)[i] = make_float2(di * acc.x, di * acc.y);
    }
}

// ---------------- fused gather-aggregate + finalize (fp16 source, fp32 accum) ----
// h[i] = relu?( dinv[i] * (g[i] + sum_{j in N(i)} g[j]) + b )
__global__ void k_gather(const float* __restrict__ bias, int do_relu) {
    int w = (blockIdx.x * blockDim.x + threadIdx.x) >> 5;
    int lane = threadIdx.x & 31;
    if (w >= N_NODES) return;

    const __half2* gp = (const __half2*)g_half;
    float2 acc = __half22float2(gp[w * 32 + lane]);   // self loop
    int s = csr_off[w], e = s + deg_buf[w];

    int k = s;
    for (; k + 8 <= e; k += 8) {
        int r0 = csr_row[k],   r1 = csr_row[k+1], r2 = csr_row[k+2], r3 = csr_row[k+3];
        int r4 = csr_row[k+4], r5 = csr_row[k+5], r6 = csr_row[k+6], r7 = csr_row[k+7];
        float2 v0 = __half22float2(__ldg(&gp[r0 * 32 + lane]));
        float2 v1 = __half22float2(__ldg(&gp[r1 * 32 + lane]));
        float2 v2 = __half22float2(__ldg(&gp[r2 * 32 + lane]));
        float2 v3 = __half22float2(__ldg(&gp[r3 * 32 + lane]));
        float2 v4 = __half22float2(__ldg(&gp[r4 * 32 + lane]));
        float2 v5 = __half22float2(__ldg(&gp[r5 * 32 + lane]));
        float2 v6 = __half22float2(__ldg(&gp[r6 * 32 + lane]));
        float2 v7 = __half22float2(__ldg(&gp[r7 * 32 + lane]));
        acc.x += ((v0.x + v1.x) + (v2.x + v3.x)) + ((v4.x + v5.x) + (v6.x + v7.x));
        acc.y += ((v0.y + v1.y) + (v2.y + v3.y)) + ((v4.y + v5.y) + (v6.y + v7.y));
    }
    for (; k < e; k++) {
        float2 v = __half22float2(__ldg(&gp[csr_row[k] * 32 + lane]));
        acc.x += v.x;
        acc.y += v.y;
    }

    float di = dinv_buf[w];
    float o0 = di * acc.x + bias[lane * 2];
    float o1 = di * acc.y + bias[lane * 2 + 1];
    if (do_relu) { o0 = fmaxf(o0, 0.f); o1 = fmaxf(o1, 0.f); }
    ((float2*)h_buf)[w * 32 + lane] = make_float2(o0, o1);
}

// ---------------- GEMM helpers (k-major Xs, FFMA2 core) ----------------
__device__ __forceinline__ void load_W(const float* __restrict__ W, float* Ws) {
    for (int i = threadIdx.x; i < HID * HID / 4; i += 256) {
        float4 w4 = ((const float4*)W)[i];
        int k = (i * 4) >> 6, f = (i * 4) & 63;
        *(float4*)(Ws + k * WLD + f) = w4;
    }
}

__device__ __forceinline__ void load_X_T(int base, float* Xs) {
    int tid = threadIdx.x;
    int node = base + tid;
    if (node < N_NODES) {
        const float4* src = (const float4*)(h_buf + node * HID);
#pragma unroll
        for (int kk = 0; kk < 16; kk++) {
            float4 v = src[kk];
            Xs[(kk * 4 + 0) * GT + tid] = v.x;
            Xs[(kk * 4 + 1) * GT + tid] = v.y;
            Xs[(kk * 4 + 2) * GT + tid] = v.z;
            Xs[(kk * 4 + 3) * GT + tid] = v.w;
        }
    } else {
#pragma unroll
        for (int kk = 0; kk < HID; kk++) Xs[kk * GT + tid] = 0.f;
    }
}

// acc2[p*8+j] = packed (out[n=tm*8+2p][f=tn*8+j], out[n=tm*8+2p+1][f=tn*8+j])
__device__ __forceinline__ void gemm_core_f2(const float* Xs, const float* Ws,
                                             unsigned long long* acc2) {
    int tid = threadIdx.x;
    int tn = tid & 7, tm = tid >> 3;
    const float* xbase = Xs + tm * 8;
    const float* wbase = Ws + tn * 8;
#pragma unroll 4
    for (int k = 0; k < HID; k++) {
        union { float4 f; unsigned long long u[2]; } xa, xb;
        xa.f = *(const float4*)(xbase + k * GT);
        xb.f = *(const float4*)(xbase + k * GT + 4);
        float4 wa = *(const float4*)(wbase + k * WLD);
        float4 wb = *(const float4*)(wbase + k * WLD + 4);
        float wr[8] = {wa.x, wa.y, wa.z, wa.w, wb.x, wb.y, wb.z, wb.w};
#pragma unroll
        for (int j = 0; j < 8; j++) {
            unsigned long long wj = bcast2(wr[j]);
            acc2[0*8+j] = ffma2(xa.u[0], wj, acc2[0*8+j]);
            acc2[1*8+j] = ffma2(xa.u[1], wj, acc2[1*8+j]);
            acc2[2*8+j] = ffma2(xb.u[0], wj, acc2[2*8+j]);
            acc2[3*8+j] = ffma2(xb.u[1], wj, acc2[3*8+j]);
        }
    }
}

// conv epilogue: g_half[n][f] = (half)(dinv[n] * acc)
__device__ __forceinline__ void conv_epilogue(int base, const unsigned long long* acc2) {
    int tid = threadIdx.x;
    int tn = tid & 7, tm = tid >> 3;
    __half2* gp = (__half2*)g_half;
#pragma unroll
    for (int p = 0; p < 4; p++) {
        float lo[8], hi[8];
#pragma unroll
        for (int j = 0; j < 8; j++) {
            float2 v = unpk(acc2[p*8+j]);
            lo[j] = v.x; hi[j] = v.y;
        }
        int n0 = base + tm * 8 + 2 * p;
        int n1 = n0 + 1;
        if (n0 < N_NODES) {
            float d0 = dinv_buf[n0];
            __half2 h0 = __floats2half2_rn(lo[0]*d0, lo[1]*d0);
            __half2 h1 = __floats2half2_rn(lo[2]*d0, lo[3]*d0);
            __half2 h2 = __floats2half2_rn(lo[4]*d0, lo[5]*d0);
            __half2 h3 = __floats2half2_rn(lo[6]*d0, lo[7]*d0);
            gp[n0 * 32 + tn * 4 + 0] = h0;
            gp[n0 * 32 + tn * 4 + 1] = h1;
            gp[n0 * 32 + tn * 4 + 2] = h2;
            gp[n0 * 32 + tn * 4 + 3] = h3;
        }
        if (n1 < N_NODES) {
            float d1 = dinv_buf[n1];
            __half2 h0 = __floats2half2_rn(hi[0]*d1, hi[1]*d1);
            __half2 h1 = __floats2half2_rn(hi[2]*d1, hi[3]*d1);
            __half2 h2 = __floats2half2_rn(hi[4]*d1, hi[5]*d1);
            __half2 h3 = __floats2half2_rn(hi[6]*d1, hi[7]*d1);
            gp[n1 * 32 + tn * 4 + 0] = h0;
            gp[n1 * 32 + tn * 4 + 1] = h1;
            gp[n1 * 32 + tn * 4 + 2] = h2;
            gp[n1 * 32 + tn * 4 + 3] = h3;
        }
    }
}

// ---------------- conv2: expand t via W1 in-reg -> k-major smem; GEMM W2 ---------
__global__ __launch_bounds__(256, 2) void k_conv2(const float* __restrict__ W1,
                                                  const float* __restrict__ b1,
                                                  const float* __restrict__ W2) {
    extern __shared__ float sm[];
    float* Xs = sm;
    float* Ws = sm + HID * GT;
    __shared__ float W1s[192];
    int tid = threadIdx.x;
    int base = blockIdx.x * GT;

    if (tid < 128) W1s[tid] = W1[tid];
    else if (tid < 192) W1s[tid] = b1[tid - 128];
    load_W(W2, Ws);

    float2 t = make_float2(0.f, 0.f);
    int node = base + tid;
    bool valid = node < N_NODES;
    if (valid) t = ((const float2*)t_buf)[node];
    __syncthreads();
#pragma unroll
    for (int k = 0; k < HID; k++) {
        float v = valid ? fmaxf(t.x * W1s[k] + t.y * W1s[64 + k] + W1s[128 + k], 0.f) : 0.f;
        Xs[k * GT + tid] = v;
    }
    __syncthreads();

    unsigned long long acc2[32];
#pragma unroll
    for (int i = 0; i < 32; i++) acc2[i] = 0ULL;
    gemm_core_f2(Xs, Ws, acc2);
    conv_epilogue(base, acc2);
}

// ---------------- conv3: X from h_buf; GEMM W3; g = dinv * X@W3 ------------------
__global__ __launch_bounds__(256, 2) void k_conv3(const float* __restrict__ W3) {
    extern __shared__ float sm[];
    float* Xs = sm;
    float* Ws = sm + HID * GT;
    int base = blockIdx.x * GT;

    load_W(W3, Ws);
    load_X_T(base, Xs);
    __syncthreads();

    unsigned long long acc2[32];
#pragma unroll
    for (int i = 0; i < 32; i++) acc2[i] = 0ULL;
    gemm_core_f2(Xs, Ws, acc2);
    conv_epilogue(base, acc2);
}

// ---------------- l45: X from h_buf; GEMM W4; out = relu(acc+b4) . W5 + b5 -------
__global__ __launch_bounds__(256, 2) void k_l45(const float* __restrict__ W4,
                                                const float* __restrict__ b4,
                                                const float* __restrict__ W5,
                                                const float* __restrict__ b5,
                                                float* __restrict__ out) {
    extern __shared__ float sm[];
    float* Xs = sm;
    float* Ws = sm + HID * GT;
    int tid = threadIdx.x;
    int base = blockIdx.x * GT;

    load_W(W4, Ws);
    load_X_T(base, Xs);
    __syncthreads();

    unsigned long long acc2[32];
#pragma unroll
    for (int i = 0; i < 32; i++) acc2[i] = 0ULL;
    gemm_core_f2(Xs, Ws, acc2);

    int tn = tid & 7, tm = tid >> 3;
    float4 b4a = __ldg((const float4*)(b4 + tn * 8));
    float4 b4b = __ldg((const float4*)(b4 + tn * 8 + 4));
    float4 w5a = __ldg((const float4*)(W5 + tn * 8));
    float4 w5b = __ldg((const float4*)(W5 + tn * 8 + 4));
    float br[8] = {b4a.x, b4a.y, b4a.z, b4a.w, b4b.x, b4b.y, b4b.z, b4b.w};
    float wr[8] = {w5a.x, w5a.y, w5a.z, w5a.w, w5b.x, w5b.y, w5b.z, w5b.w};
    float bias5 = __ldg(b5);

#pragma unroll
    for (int p = 0; p < 4; p++) {
        float v0 = 0.f, v1 = 0.f;
#pragma unroll
        for (int j = 0; j < 8; j++) {
            float2 v = unpk(acc2[p*8+j]);
            v0 += fmaxf(v.x + br[j], 0.f) * wr[j];
            v1 += fmaxf(v.y + br[j], 0.f) * wr[j];
        }
        v0 += __shfl_xor_sync(0xffffffffu, v0, 1);
        v0 += __shfl_xor_sync(0xffffffffu, v0, 2);
        v0 += __shfl_xor_sync(0xffffffffu, v0, 4);
        v1 += __shfl_xor_sync(0xffffffffu, v1, 1);
        v1 += __shfl_xor_sync(0xffffffffu, v1, 2);
        v1 += __shfl_xor_sync(0xffffffffu, v1, 4);
        if (tn == 0) {
            int n0 = base + tm * 8 + 2 * p;
            if (n0 < N_NODES)     out[n0]     = v0 + bias5;
            if (n0 + 1 < N_NODES) out[n0 + 1] = v1 + bias5;
        }
    }
}

extern "C" void kernel_launch(void* const* d_in, const int* in_sizes, int n_in,
                              void* d_out, int out_size) {
    const float* x  = (const float*)d_in[0];
    const int*   ei = (const int*)d_in[1];     // edge_index int32
    const float* W1 = (const float*)d_in[3];
    const float* b1 = (const float*)d_in[4];
    const float* W2 = (const float*)d_in[5];
    const float* b2 = (const float*)d_in[6];
    const float* W3 = (const float*)d_in[7];
    const float* b3 = (const float*)d_in[8];
    const float* W4 = (const float*)d_in[9];
    const float* b4 = (const float*)d_in[10];
    const float* W5 = (const float*)d_in[11];
    const float* b5 = (const float*)d_in[12];
    float* out = (float*)d_out;

    static int smem_set = 0;
    if (!smem_set) {
        cudaFuncSetAttribute(k_conv2, cudaFuncAttributeMaxDynamicSharedMemorySize, SMEM_GEMM);
        cudaFuncSetAttribute(k_conv3, cudaFuncAttributeMaxDynamicSharedMemorySize, SMEM_GEMM);
        cudaFuncSetAttribute(k_l45,   cudaFuncAttributeMaxDynamicSharedMemorySize, SMEM_GEMM);
        smem_set = 1;
    }

    const int nbN = (N_NODES + 255) / 256;
    const int nbE = (N_EDGES + 255) / 256;
    const int nbG = (N_NODES + GT - 1) / GT;          // 391
    const int nbW = (N_NODES * 32 + 255) / 256;       // 1 warp per node

    // CSR build + norm (+ px), fused scan
    k_zero_deg<<<nbN, 256>>>();
    k_count_deg<<<nbE, 256>>>(ei);
    k_scan_fused<<<NB_SCAN, SCAN_BS>>>(x);
    k_fill<<<nbE, 256>>>(ei);

    // conv1 aggregation (width 2)
    k_gather2<<<nbN, 256>>>();

    // conv2: expand+GEMM -> g(half) ; gather -> h
    k_conv2<<<nbG, 256, SMEM_GEMM>>>(W1, b1, W2);
    k_gather<<<nbW, 256>>>(b2, 1);
    // conv3: GEMM -> g(half) ; gather -> h
    k_conv3<<<nbG, 256, SMEM_GEMM>>>(W3);
    k_gather<<<nbW, 256>>>(b3, 0);
    // layers 4+5 fused
    k_l45<<<nbG, 256, SMEM_GEMM>>>(W4, b4, W5, b5, out);
}